// round 1
// baseline (speedup 1.0000x reference)
#include <cuda_runtime.h>
#include <cstddef>

// Problem dims (fixed by the dataset)
#define SEQ   2048
#define BATCH 2
#define EMB   1024
#define NHEAD 16
#define HDIM  64
#define FFD   4096
#define NLAYER 4
#define VOCAB 32000
#define MROWS (BATCH*SEQ)   // 4096

// ---------------- scratch (static __device__: allocation-free) ----------------
__device__ float g_h   [(size_t)MROWS * EMB];      // residual stream
__device__ float g_qkv [(size_t)MROWS * 3 * EMB];  // qkv projections
__device__ float g_attn[(size_t)MROWS * EMB];      // attention output
__device__ float g_ff  [(size_t)MROWS * FFD];      // ffn hidden
__device__ float g_t   [(size_t)MROWS * EMB];      // pre-LN temp
__device__ int   g_is64;

// ---------------- token dtype probe ----------------
// If x is int32, reading as int64 packs two tokens: value >= 2^32 unless the
// high token is exactly 0 (p ~ 1/32000 per sample). 64 samples -> certain.
__global__ void probe_kernel(const void* __restrict__ x) {
    if (threadIdx.x == 0 && blockIdx.x == 0) {
        const unsigned long long* p = (const unsigned long long*)x;
        int ok = 1;
        for (int i = 0; i < 64; i++) {
            if (p[i] >= (unsigned long long)VOCAB) { ok = 0; break; }
        }
        g_is64 = ok;
    }
}

// ---------------- embedding ----------------
__global__ __launch_bounds__(256) void embed_kernel(
    const void* __restrict__ x, const float* __restrict__ we,
    const float* __restrict__ pe)
{
    int row = blockIdx.x;              // b*SEQ + s
    int s = row & (SEQ - 1);
    long long tok = g_is64 ? ((const long long*)x)[row]
                           : (long long)((const int*)x)[row];
    const float4* wr = (const float4*)(we + (size_t)tok * EMB);
    const float4* pr = (const float4*)(pe + (size_t)s * EMB);
    float4* hr = (float4*)(g_h + (size_t)row * EMB);
    int i = threadIdx.x;               // EMB/4 == 256 == blockDim
    float4 a = wr[i], b = pr[i];
    hr[i] = make_float4(a.x + b.x, a.y + b.y, a.z + b.z, a.w + b.w);
}

// ---------------- SGEMM: C = A(MxK) @ B(KxN) [+bias][+relu] ----------------
// 128x128 tile, BK=8, 256 threads, 8x8 per thread. Requires M%128==0,
// N%128==0, K%8==0 (all shapes here satisfy this).
__global__ __launch_bounds__(256) void sgemm_nn(
    const float* __restrict__ A, const float* __restrict__ B,
    const float* __restrict__ bias, float* __restrict__ C,
    int M, int N, int K, int relu)
{
    __shared__ float As[8][128];
    __shared__ float Bs[8][128];
    int tid = threadIdx.x;
    int bx = blockIdx.x, by = blockIdx.y;
    const float* Ab = A + (size_t)by * 128 * K;
    const float* Bb = B + (size_t)bx * 128;

    int aRow = tid >> 1, aCol = (tid & 1) * 4;
    int bRow = tid >> 5, bCol = (tid & 31) * 4;
    int ty = tid >> 4, tx = tid & 15;

    float acc[8][8] = {};
    for (int k0 = 0; k0 < K; k0 += 8) {
        float4 a4 = *(const float4*)(Ab + (size_t)aRow * K + k0 + aCol);
        As[aCol + 0][aRow] = a4.x; As[aCol + 1][aRow] = a4.y;
        As[aCol + 2][aRow] = a4.z; As[aCol + 3][aRow] = a4.w;
        float4 b4 = *(const float4*)(Bb + (size_t)(k0 + bRow) * N + bCol);
        *(float4*)&Bs[bRow][bCol] = b4;
        __syncthreads();
        #pragma unroll
        for (int k = 0; k < 8; k++) {
            float ar[8], br[8];
            *(float4*)&ar[0] = *(const float4*)&As[k][ty * 8];
            *(float4*)&ar[4] = *(const float4*)&As[k][ty * 8 + 4];
            *(float4*)&br[0] = *(const float4*)&Bs[k][tx * 8];
            *(float4*)&br[4] = *(const float4*)&Bs[k][tx * 8 + 4];
            #pragma unroll
            for (int i = 0; i < 8; i++)
                #pragma unroll
                for (int j = 0; j < 8; j++)
                    acc[i][j] += ar[i] * br[j];
        }
        __syncthreads();
    }
    float* Cb = C + (size_t)(by * 128) * N + bx * 128;
    #pragma unroll
    for (int i = 0; i < 8; i++) {
        int r = ty * 8 + i;
        #pragma unroll
        for (int j = 0; j < 8; j += 4) {
            float4 v = make_float4(acc[i][j], acc[i][j+1], acc[i][j+2], acc[i][j+3]);
            if (bias) {
                int c = bx * 128 + tx * 8 + j;
                v.x += bias[c]; v.y += bias[c+1]; v.z += bias[c+2]; v.w += bias[c+3];
            }
            if (relu) {
                v.x = fmaxf(v.x, 0.f); v.y = fmaxf(v.y, 0.f);
                v.z = fmaxf(v.z, 0.f); v.w = fmaxf(v.w, 0.f);
            }
            *(float4*)(Cb + (size_t)r * N + tx * 8 + j) = v;
        }
    }
}

// ---------------- SGEMM NT: C = A(MxK) @ B(NxK)^T + bias (unembed) ----------
__global__ __launch_bounds__(256) void sgemm_nt(
    const float* __restrict__ A, const float* __restrict__ B,
    const float* __restrict__ bias, float* __restrict__ C,
    int M, int N, int K)
{
    __shared__ float As[8][128];
    __shared__ float Bs[8][128];
    int tid = threadIdx.x;
    int bx = blockIdx.x, by = blockIdx.y;
    const float* Ab = A + (size_t)by * 128 * K;
    const float* Bb = B + (size_t)bx * 128 * K;

    int aRow = tid >> 1, aCol = (tid & 1) * 4;
    int ty = tid >> 4, tx = tid & 15;

    float acc[8][8] = {};
    for (int k0 = 0; k0 < K; k0 += 8) {
        float4 a4 = *(const float4*)(Ab + (size_t)aRow * K + k0 + aCol);
        As[aCol + 0][aRow] = a4.x; As[aCol + 1][aRow] = a4.y;
        As[aCol + 2][aRow] = a4.z; As[aCol + 3][aRow] = a4.w;
        float4 b4 = *(const float4*)(Bb + (size_t)aRow * K + k0 + aCol);
        Bs[aCol + 0][aRow] = b4.x; Bs[aCol + 1][aRow] = b4.y;
        Bs[aCol + 2][aRow] = b4.z; Bs[aCol + 3][aRow] = b4.w;
        __syncthreads();
        #pragma unroll
        for (int k = 0; k < 8; k++) {
            float ar[8], br[8];
            *(float4*)&ar[0] = *(const float4*)&As[k][ty * 8];
            *(float4*)&ar[4] = *(const float4*)&As[k][ty * 8 + 4];
            *(float4*)&br[0] = *(const float4*)&Bs[k][tx * 8];
            *(float4*)&br[4] = *(const float4*)&Bs[k][tx * 8 + 4];
            #pragma unroll
            for (int i = 0; i < 8; i++)
                #pragma unroll
                for (int j = 0; j < 8; j++)
                    acc[i][j] += ar[i] * br[j];
        }
        __syncthreads();
    }
    float* Cb = C + (size_t)(by * 128) * N + bx * 128;
    #pragma unroll
    for (int i = 0; i < 8; i++) {
        int r = ty * 8 + i;
        #pragma unroll
        for (int j = 0; j < 8; j += 4) {
            int c = bx * 128 + tx * 8 + j;
            float4 v = make_float4(acc[i][j]   + bias[c],
                                   acc[i][j+1] + bias[c+1],
                                   acc[i][j+2] + bias[c+2],
                                   acc[i][j+3] + bias[c+3]);
            *(float4*)(Cb + (size_t)r * N + tx * 8 + j) = v;
        }
    }
}

// ---------------- fused causal flash-attention (fp32) ----------------
// qkv layout per row: channel = head*192 + which*64 + d ; which: 0=K,1=Q,2=V.
// Block: 8 warps, one q-row per warp; key tiles of 32; online softmax.
__global__ __launch_bounds__(256) void attn_kernel()
{
    int bh = blockIdx.y;
    int b = bh >> 4, hh = bh & 15;
    int qbase = blockIdx.x * 8;
    int w = threadIdx.x >> 5, lane = threadIdx.x & 31;
    int qrow = qbase + w;

    __shared__ float Qs[8][64];
    __shared__ float Kst[64][33];   // [d][key], padded: conflict-free lane reads
    __shared__ float Vs[32][64];

    const float* qkv = g_qkv;
    for (int i = threadIdx.x; i < 8 * 64; i += 256) {
        int r = i >> 6, d = i & 63;
        Qs[r][d] = qkv[((size_t)b * SEQ + qbase + r) * 3072 + hh * 192 + 64 + d];
    }

    float m = -1e30f, lsum = 0.f, acc0 = 0.f, acc1 = 0.f;
    for (int kt = 0; kt < qbase + 8; kt += 32) {
        __syncthreads();
        for (int i = threadIdx.x; i < 32 * 64; i += 256) {
            int kk = i >> 6, d = i & 63;
            size_t off = ((size_t)b * SEQ + kt + kk) * 3072 + hh * 192;
            Kst[d][kk] = qkv[off + d];           // K
            Vs[kk][d]  = qkv[off + 128 + d];     // V
        }
        __syncthreads();

        float s = 0.f;
        #pragma unroll
        for (int d = 0; d < 64; d++) s += Qs[w][d] * Kst[d][lane];
        s *= 0.125f;                              // 1/sqrt(64)
        if (kt + lane > qrow) s = -1e30f;         // causal mask

        float tmax = s;
        for (int o = 16; o; o >>= 1) tmax = fmaxf(tmax, __shfl_xor_sync(~0u, tmax, o));
        float mnew = fmaxf(m, tmax);
        float corr = __expf(m - mnew);
        float p = __expf(s - mnew);
        float ps = p;
        for (int o = 16; o; o >>= 1) ps += __shfl_xor_sync(~0u, ps, o);
        lsum = lsum * corr + ps;
        acc0 *= corr; acc1 *= corr;
        #pragma unroll
        for (int j = 0; j < 32; j++) {
            float pj = __shfl_sync(~0u, p, j);
            acc0 += pj * Vs[j][lane];
            acc1 += pj * Vs[j][lane + 32];
        }
        m = mnew;
    }
    float inv = 1.f / lsum;
    size_t o = ((size_t)b * SEQ + qrow) * EMB + hh * 64;
    g_attn[o + lane]      = acc0 * inv;
    g_attn[o + 32 + lane] = acc1 * inv;
}

// ---------------- fused LayerNorm + residual:  h = LN(y)*g+b + h ------------
__global__ __launch_bounds__(256) void ln_res_kernel(
    const float* __restrict__ y, const float* __restrict__ g,
    const float* __restrict__ b)
{
    int row = blockIdx.x;
    int tid = threadIdx.x;
    const float4* yr = (const float4*)(y + (size_t)row * EMB);
    float4* hr = (float4*)(g_h + (size_t)row * EMB);

    float4 v = yr[tid];
    float s  = v.x + v.y + v.z + v.w;
    float sq = v.x * v.x + v.y * v.y + v.z * v.z + v.w * v.w;
    int lane = tid & 31, wid = tid >> 5;
    for (int o = 16; o; o >>= 1) {
        s  += __shfl_xor_sync(~0u, s,  o);
        sq += __shfl_xor_sync(~0u, sq, o);
    }
    __shared__ float sh[16];
    __shared__ float mu_s, rs_s;
    if (lane == 0) { sh[wid] = s; sh[8 + wid] = sq; }
    __syncthreads();
    if (tid == 0) {
        float ts = 0.f, tq = 0.f;
        for (int i = 0; i < 8; i++) { ts += sh[i]; tq += sh[8 + i]; }
        float mu = ts * (1.f / EMB);
        float var = tq * (1.f / EMB) - mu * mu;
        mu_s = mu;
        rs_s = rsqrtf(var + 1e-6f);
    }
    __syncthreads();
    float mu = mu_s, rs = rs_s;
    const float4 gg = ((const float4*)g)[tid];
    const float4 bb = ((const float4*)b)[tid];
    float4 res = hr[tid];
    float4 out;
    out.x = (v.x - mu) * rs * gg.x + bb.x + res.x;
    out.y = (v.y - mu) * rs * gg.y + bb.y + res.y;
    out.z = (v.z - mu) * rs * gg.z + bb.z + res.z;
    out.w = (v.w - mu) * rs * gg.w + bb.w + res.w;
    hr[tid] = out;
}

// ---------------- host orchestration ----------------
extern "C" void kernel_launch(void* const* d_in, const int* in_sizes, int n_in,
                              void* d_out, int out_size)
{
    const void*  x   = d_in[0];
    const float* we  = (const float*)d_in[1];
    const float* pe  = (const float*)d_in[2];
    const float* KQV = (const float*)d_in[3];
    const float* WO  = (const float*)d_in[4];
    const float* Wup = (const float*)d_in[5];
    const float* bup = (const float*)d_in[6];
    const float* Wdn = (const float*)d_in[7];
    const float* bdn = (const float*)d_in[8];
    const float* g1  = (const float*)d_in[9];
    const float* b1  = (const float*)d_in[10];
    const float* g2  = (const float*)d_in[11];
    const float* b2  = (const float*)d_in[12];
    const float* ub  = (const float*)d_in[13];
    float* out = (float*)d_out;

    float *h, *qkv, *attn, *ff, *t;
    cudaGetSymbolAddress((void**)&h,    g_h);
    cudaGetSymbolAddress((void**)&qkv,  g_qkv);
    cudaGetSymbolAddress((void**)&attn, g_attn);
    cudaGetSymbolAddress((void**)&ff,   g_ff);
    cudaGetSymbolAddress((void**)&t,    g_t);

    probe_kernel<<<1, 32>>>(x);
    embed_kernel<<<MROWS, 256>>>(x, we, pe);

    for (int l = 0; l < NLAYER; l++) {
        // qkv = h @ KQV[l]                       (4096 x 3072 x 1024)
        sgemm_nn<<<dim3(3 * EMB / 128, MROWS / 128), 256>>>(
            h, KQV + (size_t)l * EMB * 3 * EMB, nullptr, qkv,
            MROWS, 3 * EMB, EMB, 0);
        // attn = causal_softmax(q k^T / 8) v
        attn_kernel<<<dim3(SEQ / 8, BATCH * NHEAD), 256>>>();
        // t = attn @ WO[l]                       (4096 x 1024 x 1024)
        sgemm_nn<<<dim3(EMB / 128, MROWS / 128), 256>>>(
            attn, WO + (size_t)l * EMB * EMB, nullptr, t,
            MROWS, EMB, EMB, 0);
        // h = LN(t)*g1+b1 + h
        ln_res_kernel<<<MROWS, 256>>>(t, g1 + l * EMB, b1 + l * EMB);
        // ff = relu(h @ Wup[l] + bup[l])         (4096 x 4096 x 1024)
        sgemm_nn<<<dim3(FFD / 128, MROWS / 128), 256>>>(
            h, Wup + (size_t)l * EMB * FFD, bup + (size_t)l * FFD, ff,
            MROWS, FFD, EMB, 1);
        // t = ff @ Wdn[l] + bdn[l]               (4096 x 1024 x 4096)
        sgemm_nn<<<dim3(EMB / 128, MROWS / 128), 256>>>(
            ff, Wdn + (size_t)l * FFD * EMB, bdn + (size_t)l * EMB, t,
            MROWS, EMB, FFD, 0);
        // h = LN(t)*g2+b2 + h
        ln_res_kernel<<<MROWS, 256>>>(t, g2 + l * EMB, b2 + l * EMB);
    }

    // logits = h @ we^T + ub                     (4096 x 32000 x 1024)
    sgemm_nt<<<dim3(VOCAB / 128, MROWS / 128), 256>>>(
        h, we, ub, out, MROWS, VOCAB, EMB);
}

// round 5
// speedup vs baseline: 1.3656x; 1.3656x over previous
#include <cuda_runtime.h>
#include <cuda_bf16.h>
#include <cstddef>

// Problem dims (fixed by the dataset)
#define SEQ   2048
#define BATCH 2
#define EMB   1024
#define NHEAD 16
#define HDIM  64
#define FFD   4096
#define NLAYER 4
#define VOCAB 32000
#define MROWS (BATCH*SEQ)   // 4096

// ---------------- scratch (static __device__: allocation-free) ----------------
__device__ float g_h   [(size_t)MROWS * EMB];      // residual stream
__device__ float g_qkv [(size_t)MROWS * 3 * EMB];  // qkv projections
__device__ float g_attn[(size_t)MROWS * EMB];      // attention output
__device__ float g_ff  [(size_t)MROWS * FFD];      // ffn hidden
__device__ float g_t   [(size_t)MROWS * EMB];      // pre-LN temp
__device__ int   g_is64;

// ---------------- token dtype probe ----------------
__global__ void probe_kernel(const void* __restrict__ x) {
    if (threadIdx.x == 0 && blockIdx.x == 0) {
        const unsigned long long* p = (const unsigned long long*)x;
        int ok = 1;
        for (int i = 0; i < 64; i++) {
            if (p[i] >= (unsigned long long)VOCAB) { ok = 0; break; }
        }
        g_is64 = ok;
    }
}

// ---------------- embedding ----------------
__global__ __launch_bounds__(256) void embed_kernel(
    const void* __restrict__ x, const float* __restrict__ we,
    const float* __restrict__ pe)
{
    int row = blockIdx.x;              // b*SEQ + s
    int s = row & (SEQ - 1);
    long long tok = g_is64 ? ((const long long*)x)[row]
                           : (long long)((const int*)x)[row];
    const float4* wr = (const float4*)(we + (size_t)tok * EMB);
    const float4* pr = (const float4*)(pe + (size_t)s * EMB);
    float4* hr = (float4*)(g_h + (size_t)row * EMB);
    int i = threadIdx.x;               // EMB/4 == 256 == blockDim
    float4 a = wr[i], b = pr[i];
    hr[i] = make_float4(a.x + b.x, a.y + b.y, a.z + b.z, a.w + b.w);
}

// ---------------- tensor-core GEMM: bf16 3-split (fp32-accurate) -------------
// C = A @ B (+bias)(+relu) with A MxK row-major fp32.
// TRANSB=false: B is KxN row-major.  TRANSB=true: B is NxK row-major (C=A@B^T).
// Split each fp32 into big+small bf16; compute AbBb + AbBs + AsBb on HMMA.

__device__ __forceinline__ unsigned smem_u32(const void* p) {
    return (unsigned)__cvta_generic_to_shared(p);
}

__device__ __forceinline__ void ldsm4(unsigned& r0, unsigned& r1,
                                      unsigned& r2, unsigned& r3, unsigned a) {
    asm volatile("ldmatrix.sync.aligned.m8n8.x4.shared.b16 {%0,%1,%2,%3},[%4];"
                 : "=r"(r0), "=r"(r1), "=r"(r2), "=r"(r3) : "r"(a));
}
__device__ __forceinline__ void ldsm4t(unsigned& r0, unsigned& r1,
                                       unsigned& r2, unsigned& r3, unsigned a) {
    asm volatile("ldmatrix.sync.aligned.m8n8.x4.trans.shared.b16 {%0,%1,%2,%3},[%4];"
                 : "=r"(r0), "=r"(r1), "=r"(r2), "=r"(r3) : "r"(a));
}
__device__ __forceinline__ void mma16816(float* c, const unsigned* a,
                                         const unsigned* b) {
    asm volatile(
        "mma.sync.aligned.m16n8k16.row.col.f32.bf16.bf16.f32 "
        "{%0,%1,%2,%3},{%4,%5,%6,%7},{%8,%9},{%0,%1,%2,%3};"
        : "+f"(c[0]), "+f"(c[1]), "+f"(c[2]), "+f"(c[3])
        : "r"(a[0]), "r"(a[1]), "r"(a[2]), "r"(a[3]), "r"(b[0]), "r"(b[1]));
}

template<bool TRANSB>
__global__ __launch_bounds__(256, 2) void gemm3(
    const float* __restrict__ A, const float* __restrict__ B,
    const float* __restrict__ bias, float* __restrict__ C,
    int M, int N, int K, int relu)
{
    constexpr int BR = TRANSB ? 128 : 32;    // B smem rows
    constexpr int BC = TRANSB ? 40 : 136;    // padded cols (conflict-free LDSM)
    __shared__ __nv_bfloat16 Asb[128][40];
    __shared__ __nv_bfloat16 Ass[128][40];
    __shared__ __nv_bfloat16 Bsb[BR][BC];
    __shared__ __nv_bfloat16 Bss[BR][BC];

    const int tid = threadIdx.x, lane = tid & 31, wid = tid >> 5;
    const int wm = wid >> 2, wn = wid & 3;           // 2x4 warp grid
    const int bx = blockIdx.x, by = blockIdx.y;

    // gmem staging coords
    const int ar = tid >> 1, ac0 = (tid & 1) * 16;
    const int br_ = TRANSB ? (tid >> 1) : (tid >> 3);
    const int bc0 = TRANSB ? (tid & 1) * 16 : (tid & 7) * 16;

    // per-lane ldmatrix addresses
    unsigned a_ab, a_as;
    {
        int r = wm * 64 + (lane & 15);
        int c = (lane >> 4) * 8;
        a_ab = smem_u32(&Asb[r][c]);
        a_as = smem_u32(&Ass[r][c]);
    }
    unsigned b_ab, b_as;
    if (TRANSB) {
        int r = wn * 32 + (lane >> 4) * 8 + (lane & 7);
        int c = ((lane >> 3) & 1) * 8;
        b_ab = smem_u32(&Bsb[r][c]);
        b_as = smem_u32(&Bss[r][c]);
    } else {
        int r = ((lane >> 3) & 1) * 8 + (lane & 7);
        int c = wn * 32 + (lane >> 4) * 8;
        b_ab = smem_u32(&Bsb[r][c]);
        b_as = smem_u32(&Bss[r][c]);
    }
    constexpr unsigned A_MT = 16u * 40 * 2;                 // m-tile stride
    constexpr unsigned A_KS = 32u;                          // k-step 16 bf16
    constexpr unsigned B_KS = TRANSB ? 32u : 16u * 136 * 2; // k-step
    constexpr unsigned B_NT = TRANSB ? 16u * 40 * 2 : 32u;  // 16-col n step

    float acc[4][4][4];
    #pragma unroll
    for (int i = 0; i < 4; i++)
        #pragma unroll
        for (int j = 0; j < 4; j++)
            #pragma unroll
            for (int q = 0; q < 4; q++) acc[i][j][q] = 0.f;

    for (int k0 = 0; k0 < K; k0 += 32) {
        // ---- stage A (fp32 -> big/small bf16) ----
        {
            const float4* ap =
                (const float4*)(A + (size_t)(by * 128 + ar) * K + k0 + ac0);
            #pragma unroll
            for (int i = 0; i < 4; i++) {
                float4 v = ap[i];
                int c = ac0 + i * 4;
                float f[4] = {v.x, v.y, v.z, v.w};
                #pragma unroll
                for (int j = 0; j < 4; j++) {
                    __nv_bfloat16 hb = __float2bfloat16(f[j]);
                    Asb[ar][c + j] = hb;
                    Ass[ar][c + j] = __float2bfloat16(f[j] - __bfloat162float(hb));
                }
            }
        }
        // ---- stage B ----
        {
            const float4* bp = TRANSB
                ? (const float4*)(B + (size_t)(bx * 128 + br_) * K + k0 + bc0)
                : (const float4*)(B + (size_t)(k0 + br_) * N + bx * 128 + bc0);
            #pragma unroll
            for (int i = 0; i < 4; i++) {
                float4 v = bp[i];
                int c = bc0 + i * 4;
                float f[4] = {v.x, v.y, v.z, v.w};
                #pragma unroll
                for (int j = 0; j < 4; j++) {
                    __nv_bfloat16 hb = __float2bfloat16(f[j]);
                    Bsb[br_][c + j] = hb;
                    Bss[br_][c + j] = __float2bfloat16(f[j] - __bfloat162float(hb));
                }
            }
        }
        __syncthreads();

        #pragma unroll
        for (int ks = 0; ks < 2; ks++) {
            unsigned a[4][4], bb[4][2], bs[4][2];
            // A big fragments
            #pragma unroll
            for (int mt = 0; mt < 4; mt++)
                ldsm4(a[mt][0], a[mt][1], a[mt][2], a[mt][3],
                      a_ab + mt * A_MT + ks * A_KS);
            // B big fragments (2 ldmatrix.x4 cover 4 n-tiles)
            #pragma unroll
            for (int n2 = 0; n2 < 2; n2++) {
                unsigned r0, r1, r2, r3;
                if (TRANSB) ldsm4 (r0, r1, r2, r3, b_ab + ks * B_KS + n2 * B_NT);
                else        ldsm4t(r0, r1, r2, r3, b_ab + ks * B_KS + n2 * B_NT);
                bb[2 * n2][0] = r0; bb[2 * n2][1] = r1;
                bb[2 * n2 + 1][0] = r2; bb[2 * n2 + 1][1] = r3;
            }
            // term 1: Ab * Bb
            #pragma unroll
            for (int mt = 0; mt < 4; mt++)
                #pragma unroll
                for (int nt = 0; nt < 4; nt++)
                    mma16816(acc[mt][nt], a[mt], bb[nt]);
            // B small fragments; term 2: Ab * Bs
            #pragma unroll
            for (int n2 = 0; n2 < 2; n2++) {
                unsigned r0, r1, r2, r3;
                if (TRANSB) ldsm4 (r0, r1, r2, r3, b_as + ks * B_KS + n2 * B_NT);
                else        ldsm4t(r0, r1, r2, r3, b_as + ks * B_KS + n2 * B_NT);
                bs[2 * n2][0] = r0; bs[2 * n2][1] = r1;
                bs[2 * n2 + 1][0] = r2; bs[2 * n2 + 1][1] = r3;
            }
            #pragma unroll
            for (int mt = 0; mt < 4; mt++)
                #pragma unroll
                for (int nt = 0; nt < 4; nt++)
                    mma16816(acc[mt][nt], a[mt], bs[nt]);
            // A small fragments (reuse regs); term 3: As * Bb
            #pragma unroll
            for (int mt = 0; mt < 4; mt++)
                ldsm4(a[mt][0], a[mt][1], a[mt][2], a[mt][3],
                      a_as + mt * A_MT + ks * A_KS);
            #pragma unroll
            for (int mt = 0; mt < 4; mt++)
                #pragma unroll
                for (int nt = 0; nt < 4; nt++)
                    mma16816(acc[mt][nt], a[mt], bb[nt]);
        }
        __syncthreads();
    }

    // ---- epilogue ----
    const int g = lane >> 2, t2 = (lane & 3) * 2;
    #pragma unroll
    for (int mt = 0; mt < 4; mt++) {
        int row = by * 128 + wm * 64 + mt * 16 + g;
        #pragma unroll
        for (int nt = 0; nt < 4; nt++) {
            int col = bx * 128 + wn * 32 + nt * 8 + t2;
            float bb0 = 0.f, bb1 = 0.f;
            if (bias) { bb0 = bias[col]; bb1 = bias[col + 1]; }
            float v0 = acc[mt][nt][0] + bb0, v1 = acc[mt][nt][1] + bb1;
            float v2 = acc[mt][nt][2] + bb0, v3 = acc[mt][nt][3] + bb1;
            if (relu) {
                v0 = fmaxf(v0, 0.f); v1 = fmaxf(v1, 0.f);
                v2 = fmaxf(v2, 0.f); v3 = fmaxf(v3, 0.f);
            }
            *(float2*)(C + (size_t)row * N + col) = make_float2(v0, v1);
            *(float2*)(C + (size_t)(row + 8) * N + col) = make_float2(v2, v3);
        }
    }
}

// ---------------- fused causal flash-attention (fp32) ----------------
__global__ __launch_bounds__(256) void attn_kernel()
{
    int bh = blockIdx.y;
    int b = bh >> 4, hh = bh & 15;
    int qbase = blockIdx.x * 8;
    int w = threadIdx.x >> 5, lane = threadIdx.x & 31;
    int qrow = qbase + w;

    __shared__ float Qs[8][64];
    __shared__ float Kst[64][33];
    __shared__ float Vs[32][64];

    const float* qkv = g_qkv;
    for (int i = threadIdx.x; i < 8 * 64; i += 256) {
        int r = i >> 6, d = i & 63;
        Qs[r][d] = qkv[((size_t)b * SEQ + qbase + r) * 3072 + hh * 192 + 64 + d];
    }

    float m = -1e30f, lsum = 0.f, acc0 = 0.f, acc1 = 0.f;
    for (int kt = 0; kt < qbase + 8; kt += 32) {
        __syncthreads();
        for (int i = threadIdx.x; i < 32 * 64; i += 256) {
            int kk = i >> 6, d = i & 63;
            size_t off = ((size_t)b * SEQ + kt + kk) * 3072 + hh * 192;
            Kst[d][kk] = qkv[off + d];           // K
            Vs[kk][d]  = qkv[off + 128 + d];     // V
        }
        __syncthreads();

        float s = 0.f;
        #pragma unroll
        for (int d = 0; d < 64; d++) s += Qs[w][d] * Kst[d][lane];
        s *= 0.125f;
        if (kt + lane > qrow) s = -1e30f;

        float tmax = s;
        for (int o = 16; o; o >>= 1) tmax = fmaxf(tmax, __shfl_xor_sync(~0u, tmax, o));
        float mnew = fmaxf(m, tmax);
        float corr = __expf(m - mnew);
        float p = __expf(s - mnew);
        float ps = p;
        for (int o = 16; o; o >>= 1) ps += __shfl_xor_sync(~0u, ps, o);
        lsum = lsum * corr + ps;
        acc0 *= corr; acc1 *= corr;
        #pragma unroll
        for (int j = 0; j < 32; j++) {
            float pj = __shfl_sync(~0u, p, j);
            acc0 += pj * Vs[j][lane];
            acc1 += pj * Vs[j][lane + 32];
        }
        m = mnew;
    }
    float inv = 1.f / lsum;
    size_t o = ((size_t)b * SEQ + qrow) * EMB + hh * 64;
    g_attn[o + lane]      = acc0 * inv;
    g_attn[o + 32 + lane] = acc1 * inv;
}

// ---------------- fused LayerNorm + residual ----------------
__global__ __launch_bounds__(256) void ln_res_kernel(
    const float* __restrict__ y, const float* __restrict__ g,
    const float* __restrict__ b)
{
    int row = blockIdx.x;
    int tid = threadIdx.x;
    const float4* yr = (const float4*)(y + (size_t)row * EMB);
    float4* hr = (float4*)(g_h + (size_t)row * EMB);

    float4 v = yr[tid];
    float s  = v.x + v.y + v.z + v.w;
    float sq = v.x * v.x + v.y * v.y + v.z * v.z + v.w * v.w;
    int lane = tid & 31, wid = tid >> 5;
    for (int o = 16; o; o >>= 1) {
        s  += __shfl_xor_sync(~0u, s,  o);
        sq += __shfl_xor_sync(~0u, sq, o);
    }
    __shared__ float sh[16];
    __shared__ float mu_s, rs_s;
    if (lane == 0) { sh[wid] = s; sh[8 + wid] = sq; }
    __syncthreads();
    if (tid == 0) {
        float ts = 0.f, tq = 0.f;
        for (int i = 0; i < 8; i++) { ts += sh[i]; tq += sh[8 + i]; }
        float mu = ts * (1.f / EMB);
        float var = tq * (1.f / EMB) - mu * mu;
        mu_s = mu;
        rs_s = rsqrtf(var + 1e-6f);
    }
    __syncthreads();
    float mu = mu_s, rs = rs_s;
    const float4 gg = ((const float4*)g)[tid];
    const float4 bb = ((const float4*)b)[tid];
    float4 res = hr[tid];
    float4 out;
    out.x = (v.x - mu) * rs * gg.x + bb.x + res.x;
    out.y = (v.y - mu) * rs * gg.y + bb.y + res.y;
    out.z = (v.z - mu) * rs * gg.z + bb.z + res.z;
    out.w = (v.w - mu) * rs * gg.w + bb.w + res.w;
    hr[tid] = out;
}

// ---------------- host orchestration ----------------
extern "C" void kernel_launch(void* const* d_in, const int* in_sizes, int n_in,
                              void* d_out, int out_size)
{
    const void*  x   = d_in[0];
    const float* we  = (const float*)d_in[1];
    const float* pe  = (const float*)d_in[2];
    const float* KQV = (const float*)d_in[3];
    const float* WO  = (const float*)d_in[4];
    const float* Wup = (const float*)d_in[5];
    const float* bup = (const float*)d_in[6];
    const float* Wdn = (const float*)d_in[7];
    const float* bdn = (const float*)d_in[8];
    const float* g1  = (const float*)d_in[9];
    const float* b1  = (const float*)d_in[10];
    const float* g2  = (const float*)d_in[11];
    const float* b2  = (const float*)d_in[12];
    const float* ub  = (const float*)d_in[13];
    float* out = (float*)d_out;

    float *h, *qkv, *attn, *ff, *t;
    cudaGetSymbolAddress((void**)&h,    g_h);
    cudaGetSymbolAddress((void**)&qkv,  g_qkv);
    cudaGetSymbolAddress((void**)&attn, g_attn);
    cudaGetSymbolAddress((void**)&ff,   g_ff);
    cudaGetSymbolAddress((void**)&t,    g_t);

    probe_kernel<<<1, 32>>>(x);
    embed_kernel<<<MROWS, 256>>>(x, we, pe);

    for (int l = 0; l < NLAYER; l++) {
        // qkv = h @ KQV[l]                       (4096 x 3072 x 1024)
        gemm3<false><<<dim3(3 * EMB / 128, MROWS / 128), 256>>>(
            h, KQV + (size_t)l * EMB * 3 * EMB, nullptr, qkv,
            MROWS, 3 * EMB, EMB, 0);
        // attn = causal_softmax(q k^T / 8) v
        attn_kernel<<<dim3(SEQ / 8, BATCH * NHEAD), 256>>>();
        // t = attn @ WO[l]                       (4096 x 1024 x 1024)
        gemm3<false><<<dim3(EMB / 128, MROWS / 128), 256>>>(
            attn, WO + (size_t)l * EMB * EMB, nullptr, t,
            MROWS, EMB, EMB, 0);
        // h = LN(t)*g1+b1 + h
        ln_res_kernel<<<MROWS, 256>>>(t, g1 + l * EMB, b1 + l * EMB);
        // ff = relu(h @ Wup[l] + bup[l])         (4096 x 4096 x 1024)
        gemm3<false><<<dim3(FFD / 128, MROWS / 128), 256>>>(
            h, Wup + (size_t)l * EMB * FFD, bup + (size_t)l * FFD, ff,
            MROWS, FFD, EMB, 1);
        // t = ff @ Wdn[l] + bdn[l]               (4096 x 1024 x 4096)
        gemm3<false><<<dim3(EMB / 128, MROWS / 128), 256>>>(
            ff, Wdn + (size_t)l * FFD * EMB, bdn + (size_t)l * EMB, t,
            MROWS, EMB, FFD, 0);
        // h = LN(t)*g2+b2 + h
        ln_res_kernel<<<MROWS, 256>>>(t, g2 + l * EMB, b2 + l * EMB);
    }

    // logits = h @ we^T + ub                     (4096 x 32000 x 1024)
    gemm3<true><<<dim3(VOCAB / 128, MROWS / 128), 256>>>(
        h, we, ub, out, MROWS, VOCAB, EMB, 0);
}

// round 7
// speedup vs baseline: 1.8797x; 1.3765x over previous
#include <cuda_runtime.h>
#include <cuda_bf16.h>
#include <cstddef>

// Problem dims (fixed by the dataset)
#define SEQ   2048
#define BATCH 2
#define EMB   1024
#define NHEAD 16
#define HDIM  64
#define FFD   4096
#define NLAYER 4
#define VOCAB 32000
#define MROWS (BATCH*SEQ)   // 4096

typedef __nv_bfloat16 bf16;

// ---------------- scratch (static __device__: allocation-free) ----------------
__device__ float g_h  [(size_t)MROWS * EMB];        // residual stream fp32
__device__ float g_qkv[(size_t)MROWS * 3 * EMB];    // qkv projections fp32
__device__ float g_t  [(size_t)MROWS * EMB];        // pre-LN temp fp32
__device__ int   g_is64;

// bf16 big/small pairs: activations
__device__ bf16 g_hb [(size_t)MROWS * EMB],  g_hs [(size_t)MROWS * EMB];
__device__ bf16 g_atb[(size_t)MROWS * EMB],  g_ats[(size_t)MROWS * EMB];
__device__ bf16 g_ffb[(size_t)MROWS * FFD],  g_ffs[(size_t)MROWS * FFD];
// bf16 big/small pairs: weights (split once per launch)
__device__ bf16 g_KQVb[(size_t)NLAYER*EMB*3*EMB], g_KQVs[(size_t)NLAYER*EMB*3*EMB];
__device__ bf16 g_WOb [(size_t)NLAYER*EMB*EMB],   g_WOs [(size_t)NLAYER*EMB*EMB];
__device__ bf16 g_Wub [(size_t)NLAYER*EMB*FFD],   g_Wus [(size_t)NLAYER*EMB*FFD];
__device__ bf16 g_Wdb [(size_t)NLAYER*FFD*EMB],   g_Wds [(size_t)NLAYER*FFD*EMB];
__device__ bf16 g_web [(size_t)VOCAB*EMB],        g_wes [(size_t)VOCAB*EMB];

// ---------------- token dtype probe ----------------
__global__ void probe_kernel(const void* __restrict__ x) {
    if (threadIdx.x == 0 && blockIdx.x == 0) {
        const unsigned long long* p = (const unsigned long long*)x;
        int ok = 1;
        for (int i = 0; i < 64; i++)
            if (p[i] >= (unsigned long long)VOCAB) { ok = 0; break; }
        g_is64 = ok;
    }
}

// ---------------- fp32 -> (big, small) bf16 splitter ----------------
__device__ __forceinline__ void split1(float v, bf16& b, bf16& s) {
    b = __float2bfloat16(v);
    s = __float2bfloat16(v - __bfloat162float(b));
}

__global__ __launch_bounds__(256) void split_kernel(
    const float* __restrict__ src, bf16* __restrict__ db,
    bf16* __restrict__ ds, size_t n)
{
    size_t i = ((size_t)blockIdx.x * 256 + threadIdx.x) * 4;
    size_t stride = (size_t)gridDim.x * 1024;
    for (; i < n; i += stride) {
        float4 v = *(const float4*)(src + i);
        bf16 b0,s0,b1,s1,b2,s2,b3,s3;
        split1(v.x,b0,s0); split1(v.y,b1,s1); split1(v.z,b2,s2); split1(v.w,b3,s3);
        *(__nv_bfloat162*)(db+i)   = __nv_bfloat162(b0,b1);
        *(__nv_bfloat162*)(db+i+2) = __nv_bfloat162(b2,b3);
        *(__nv_bfloat162*)(ds+i)   = __nv_bfloat162(s0,s1);
        *(__nv_bfloat162*)(ds+i+2) = __nv_bfloat162(s2,s3);
    }
}

// ---------------- embedding (writes fp32 h + bf16 pair) ----------------
__global__ __launch_bounds__(256) void embed_kernel(
    const void* __restrict__ x, const float* __restrict__ we,
    const float* __restrict__ pe)
{
    int row = blockIdx.x;
    int s = row & (SEQ - 1);
    long long tok = g_is64 ? ((const long long*)x)[row]
                           : (long long)((const int*)x)[row];
    const float4* wr = (const float4*)(we + (size_t)tok * EMB);
    const float4* pr = (const float4*)(pe + (size_t)s * EMB);
    int i = threadIdx.x;
    float4 a = wr[i], b = pr[i];
    float4 v = make_float4(a.x+b.x, a.y+b.y, a.z+b.z, a.w+b.w);
    ((float4*)(g_h + (size_t)row * EMB))[i] = v;
    size_t o = (size_t)row * EMB + i * 4;
    bf16 b0,s0,b1,s1,b2,s2,b3,s3;
    split1(v.x,b0,s0); split1(v.y,b1,s1); split1(v.z,b2,s2); split1(v.w,b3,s3);
    *(__nv_bfloat162*)(g_hb+o)   = __nv_bfloat162(b0,b1);
    *(__nv_bfloat162*)(g_hb+o+2) = __nv_bfloat162(b2,b3);
    *(__nv_bfloat162*)(g_hs+o)   = __nv_bfloat162(s0,s1);
    *(__nv_bfloat162*)(g_hs+o+2) = __nv_bfloat162(s2,s3);
}

// ---------------- tensor-core GEMM, pre-split bf16 operands ----------------
// C = A@B (+bias)(+relu), 3-term: AbBb + AbBs + AsBb.
// TRANSB=false: B KxN row-major.  TRANSB=true: B NxK row-major (C=A@B^T).
// cp.async double-buffered. Outputs: fp32 Cf and/or bf16 pair (Cb,Cs).

__device__ __forceinline__ unsigned smem_u32(const void* p) {
    return (unsigned)__cvta_generic_to_shared(p);
}
__device__ __forceinline__ void cpa16(unsigned d, const void* s) {
    asm volatile("cp.async.cg.shared.global [%0],[%1],16;\n"::"r"(d),"l"(s));
}
__device__ __forceinline__ void cpa_commit() {
    asm volatile("cp.async.commit_group;\n");
}
template<int W> __device__ __forceinline__ void cpa_wait() {
    asm volatile("cp.async.wait_group %0;\n"::"n"(W));
}
__device__ __forceinline__ void ldsm4(unsigned& r0, unsigned& r1,
                                      unsigned& r2, unsigned& r3, unsigned a) {
    asm volatile("ldmatrix.sync.aligned.m8n8.x4.shared.b16 {%0,%1,%2,%3},[%4];"
                 : "=r"(r0), "=r"(r1), "=r"(r2), "=r"(r3) : "r"(a));
}
__device__ __forceinline__ void ldsm4t(unsigned& r0, unsigned& r1,
                                       unsigned& r2, unsigned& r3, unsigned a) {
    asm volatile("ldmatrix.sync.aligned.m8n8.x4.trans.shared.b16 {%0,%1,%2,%3},[%4];"
                 : "=r"(r0), "=r"(r1), "=r"(r2), "=r"(r3) : "r"(a));
}
__device__ __forceinline__ void mma16816(float* c, const unsigned* a,
                                         const unsigned* b) {
    asm volatile(
        "mma.sync.aligned.m16n8k16.row.col.f32.bf16.bf16.f32 "
        "{%0,%1,%2,%3},{%4,%5,%6,%7},{%8,%9},{%0,%1,%2,%3};"
        : "+f"(c[0]), "+f"(c[1]), "+f"(c[2]), "+f"(c[3])
        : "r"(a[0]), "r"(a[1]), "r"(a[2]), "r"(a[3]), "r"(b[0]), "r"(b[1]));
}

template<bool TRANSB>
__global__ __launch_bounds__(256, 2) void gemmp(
    const bf16* __restrict__ Ab, const bf16* __restrict__ As,
    const bf16* __restrict__ Bb, const bf16* __restrict__ Bs,
    const float* __restrict__ bias, float* __restrict__ Cf,
    bf16* __restrict__ Cb, bf16* __restrict__ Cs,
    int M, int N, int K, int relu)
{
    extern __shared__ bf16 dyn[];
    constexpr unsigned ASTG = 128u * 40 * 2;                    // bytes/stage
    constexpr unsigned BSTG = TRANSB ? 128u * 40 * 2 : 32u * 136 * 2;
    constexpr unsigned ABIG = 0, ASMO = 2 * ASTG;
    constexpr unsigned BBIG = 4 * ASTG, BSMO = BBIG + 2 * BSTG;

    const int tid = threadIdx.x, lane = tid & 31, wid = tid >> 5;
    const int wm = wid >> 2, wn = wid & 3;
    const int bx = blockIdx.x, by = blockIdx.y;
    const unsigned s0 = smem_u32(dyn);

    // per-lane ldmatrix offsets (within a stage)
    const unsigned a_off = ((wm * 64 + (lane & 15)) * 40 + (lane >> 4) * 8) * 2;
    const unsigned b_off = TRANSB
        ? ((wn * 32 + (lane >> 4) * 8 + (lane & 7)) * 40 + ((lane >> 3) & 1) * 8) * 2
        : ((((lane >> 3) & 1) * 8 + (lane & 7)) * 136 + wn * 32 + (lane >> 4) * 8) * 2;
    constexpr unsigned A_MT = 16u * 40 * 2;
    constexpr unsigned A_KS = 32u;
    constexpr unsigned B_KS = TRANSB ? 32u : 16u * 136 * 2;
    constexpr unsigned B_NT = TRANSB ? 16u * 40 * 2 : 32u;

    float acc[4][4][4];
    #pragma unroll
    for (int i = 0; i < 4; i++)
        #pragma unroll
        for (int j = 0; j < 4; j++)
            #pragma unroll
            for (int q = 0; q < 4; q++) acc[i][j][q] = 0.f;

    auto loadA = [&](int k0, int st) {
        #pragma unroll
        for (int c2 = 0; c2 < 2; c2++) {
            int ch = tid + c2 * 256;
            int row = ch >> 2, col = (ch & 3) * 8;
            size_t g = (size_t)(by * 128 + row) * K + k0 + col;
            unsigned off = (unsigned)(row * 40 + col) * 2;
            cpa16(s0 + ABIG + st * ASTG + off, Ab + g);
            cpa16(s0 + ASMO + st * ASTG + off, As + g);
        }
    };
    auto loadB = [&](int k0, int st) {
        #pragma unroll
        for (int c2 = 0; c2 < 2; c2++) {
            int ch = tid + c2 * 256;
            if (TRANSB) {
                int row = ch >> 2, col = (ch & 3) * 8;
                size_t g = (size_t)(bx * 128 + row) * K + k0 + col;
                unsigned off = (unsigned)(row * 40 + col) * 2;
                cpa16(s0 + BBIG + st * BSTG + off, Bb + g);
                cpa16(s0 + BSMO + st * BSTG + off, Bs + g);
            } else {
                int row = ch >> 4, col = (ch & 15) * 8;
                size_t g = (size_t)(k0 + row) * N + bx * 128 + col;
                unsigned off = (unsigned)(row * 136 + col) * 2;
                cpa16(s0 + BBIG + st * BSTG + off, Bb + g);
                cpa16(s0 + BSMO + st * BSTG + off, Bs + g);
            }
        }
    };

    const int T = K >> 5;
    loadA(0, 0); loadB(0, 0); cpa_commit();

    for (int i = 0; i < T; i++) {
        if (i + 1 < T) {
            int st = (i + 1) & 1;
            loadA((i + 1) << 5, st); loadB((i + 1) << 5, st); cpa_commit();
            cpa_wait<1>();
        } else {
            cpa_wait<0>();
        }
        __syncthreads();

        const int st = i & 1;
        const unsigned a_ab = s0 + ABIG + st * ASTG + a_off;
        const unsigned a_as = s0 + ASMO + st * ASTG + a_off;
        const unsigned b_ab = s0 + BBIG + st * BSTG + b_off;
        const unsigned b_as = s0 + BSMO + st * BSTG + b_off;

        #pragma unroll
        for (int ks = 0; ks < 2; ks++) {
            unsigned a[4][4], bb[4][2], bs[4][2];
            #pragma unroll
            for (int mt = 0; mt < 4; mt++)
                ldsm4(a[mt][0], a[mt][1], a[mt][2], a[mt][3],
                      a_ab + mt * A_MT + ks * A_KS);
            #pragma unroll
            for (int n2 = 0; n2 < 2; n2++) {
                unsigned r0, r1, r2, r3;
                if (TRANSB) ldsm4 (r0, r1, r2, r3, b_ab + ks * B_KS + n2 * B_NT);
                else        ldsm4t(r0, r1, r2, r3, b_ab + ks * B_KS + n2 * B_NT);
                bb[2*n2][0] = r0; bb[2*n2][1] = r1;
                bb[2*n2+1][0] = r2; bb[2*n2+1][1] = r3;
            }
            #pragma unroll
            for (int mt = 0; mt < 4; mt++)
                #pragma unroll
                for (int nt = 0; nt < 4; nt++)
                    mma16816(acc[mt][nt], a[mt], bb[nt]);
            #pragma unroll
            for (int n2 = 0; n2 < 2; n2++) {
                unsigned r0, r1, r2, r3;
                if (TRANSB) ldsm4 (r0, r1, r2, r3, b_as + ks * B_KS + n2 * B_NT);
                else        ldsm4t(r0, r1, r2, r3, b_as + ks * B_KS + n2 * B_NT);
                bs[2*n2][0] = r0; bs[2*n2][1] = r1;
                bs[2*n2+1][0] = r2; bs[2*n2+1][1] = r3;
            }
            #pragma unroll
            for (int mt = 0; mt < 4; mt++)
                #pragma unroll
                for (int nt = 0; nt < 4; nt++)
                    mma16816(acc[mt][nt], a[mt], bs[nt]);
            #pragma unroll
            for (int mt = 0; mt < 4; mt++)
                ldsm4(a[mt][0], a[mt][1], a[mt][2], a[mt][3],
                      a_as + mt * A_MT + ks * A_KS);
            #pragma unroll
            for (int mt = 0; mt < 4; mt++)
                #pragma unroll
                for (int nt = 0; nt < 4; nt++)
                    mma16816(acc[mt][nt], a[mt], bb[nt]);
        }
        __syncthreads();
    }

    // ---- epilogue ----
    const int g = lane >> 2, t2 = (lane & 3) * 2;
    #pragma unroll
    for (int mt = 0; mt < 4; mt++) {
        int row = by * 128 + wm * 64 + mt * 16 + g;
        #pragma unroll
        for (int nt = 0; nt < 4; nt++) {
            int col = bx * 128 + wn * 32 + nt * 8 + t2;
            float bb0 = 0.f, bb1 = 0.f;
            if (bias) { bb0 = bias[col]; bb1 = bias[col + 1]; }
            float v0 = acc[mt][nt][0] + bb0, v1 = acc[mt][nt][1] + bb1;
            float v2 = acc[mt][nt][2] + bb0, v3 = acc[mt][nt][3] + bb1;
            if (relu) {
                v0 = fmaxf(v0, 0.f); v1 = fmaxf(v1, 0.f);
                v2 = fmaxf(v2, 0.f); v3 = fmaxf(v3, 0.f);
            }
            if (Cf) {
                *(float2*)(Cf + (size_t)row * N + col) = make_float2(v0, v1);
                *(float2*)(Cf + (size_t)(row + 8) * N + col) = make_float2(v2, v3);
            }
            if (Cb) {
                bf16 hb0,hs0,hb1,hs1,hb2,hs2,hb3,hs3;
                split1(v0,hb0,hs0); split1(v1,hb1,hs1);
                split1(v2,hb2,hs2); split1(v3,hb3,hs3);
                *(__nv_bfloat162*)(Cb + (size_t)row * N + col)     = __nv_bfloat162(hb0,hb1);
                *(__nv_bfloat162*)(Cb + (size_t)(row+8) * N + col) = __nv_bfloat162(hb2,hb3);
                *(__nv_bfloat162*)(Cs + (size_t)row * N + col)     = __nv_bfloat162(hs0,hs1);
                *(__nv_bfloat162*)(Cs + (size_t)(row+8) * N + col) = __nv_bfloat162(hs2,hs3);
            }
        }
    }
}

// ---------------- fused causal flash-attention (fp32, pair output) ----------
__global__ __launch_bounds__(256) void attn_kernel()
{
    int bh = blockIdx.y;
    int b = bh >> 4, hh = bh & 15;
    int qbase = blockIdx.x * 8;
    int w = threadIdx.x >> 5, lane = threadIdx.x & 31;
    int qrow = qbase + w;

    __shared__ float Qs[8][64];
    __shared__ float Kst[64][33];
    __shared__ float Vs[32][64];

    const float* qkv = g_qkv;
    for (int i = threadIdx.x; i < 8 * 64; i += 256) {
        int r = i >> 6, d = i & 63;
        Qs[r][d] = qkv[((size_t)b * SEQ + qbase + r) * 3072 + hh * 192 + 64 + d];
    }

    float m = -1e30f, lsum = 0.f, acc0 = 0.f, acc1 = 0.f;
    for (int kt = 0; kt < qbase + 8; kt += 32) {
        __syncthreads();
        for (int i = threadIdx.x; i < 32 * 64; i += 256) {
            int kk = i >> 6, d = i & 63;
            size_t off = ((size_t)b * SEQ + kt + kk) * 3072 + hh * 192;
            Kst[d][kk] = qkv[off + d];
            Vs[kk][d]  = qkv[off + 128 + d];
        }
        __syncthreads();

        float s = 0.f;
        #pragma unroll
        for (int d = 0; d < 64; d++) s += Qs[w][d] * Kst[d][lane];
        s *= 0.125f;
        if (kt + lane > qrow) s = -1e30f;

        float tmax = s;
        for (int o = 16; o; o >>= 1) tmax = fmaxf(tmax, __shfl_xor_sync(~0u, tmax, o));
        float mnew = fmaxf(m, tmax);
        float corr = __expf(m - mnew);
        float p = __expf(s - mnew);
        float ps = p;
        for (int o = 16; o; o >>= 1) ps += __shfl_xor_sync(~0u, ps, o);
        lsum = lsum * corr + ps;
        acc0 *= corr; acc1 *= corr;
        #pragma unroll
        for (int j = 0; j < 32; j++) {
            float pj = __shfl_sync(~0u, p, j);
            acc0 += pj * Vs[j][lane];
            acc1 += pj * Vs[j][lane + 32];
        }
        m = mnew;
    }
    float inv = 1.f / lsum;
    size_t o = ((size_t)b * SEQ + qrow) * EMB + hh * 64;
    bf16 b0,s0,b1,s1;
    split1(acc0 * inv, b0, s0);
    split1(acc1 * inv, b1, s1);
    g_atb[o + lane] = b0;       g_ats[o + lane] = s0;
    g_atb[o + 32 + lane] = b1;  g_ats[o + 32 + lane] = s1;
}

// ---------------- fused LayerNorm + residual (writes fp32 h + pair) ---------
__global__ __launch_bounds__(256) void ln_res_kernel(
    const float* __restrict__ y, const float* __restrict__ g,
    const float* __restrict__ b)
{
    int row = blockIdx.x;
    int tid = threadIdx.x;
    const float4* yr = (const float4*)(y + (size_t)row * EMB);
    float4* hr = (float4*)(g_h + (size_t)row * EMB);

    float4 v = yr[tid];
    float s  = v.x + v.y + v.z + v.w;
    float sq = v.x*v.x + v.y*v.y + v.z*v.z + v.w*v.w;
    int lane = tid & 31, wid = tid >> 5;
    for (int o = 16; o; o >>= 1) {
        s  += __shfl_xor_sync(~0u, s,  o);
        sq += __shfl_xor_sync(~0u, sq, o);
    }
    __shared__ float sh[16];
    __shared__ float mu_s, rs_s;
    if (lane == 0) { sh[wid] = s; sh[8 + wid] = sq; }
    __syncthreads();
    if (tid == 0) {
        float ts = 0.f, tq = 0.f;
        for (int i = 0; i < 8; i++) { ts += sh[i]; tq += sh[8 + i]; }
        float mu = ts * (1.f / EMB);
        float var = tq * (1.f / EMB) - mu * mu;
        mu_s = mu;
        rs_s = rsqrtf(var + 1e-6f);
    }
    __syncthreads();
    float mu = mu_s, rs = rs_s;
    const float4 gg = ((const float4*)g)[tid];
    const float4 bb = ((const float4*)b)[tid];
    float4 res = hr[tid];
    float4 out;
    out.x = (v.x - mu) * rs * gg.x + bb.x + res.x;
    out.y = (v.y - mu) * rs * gg.y + bb.y + res.y;
    out.z = (v.z - mu) * rs * gg.z + bb.z + res.z;
    out.w = (v.w - mu) * rs * gg.w + bb.w + res.w;
    hr[tid] = out;
    size_t o = (size_t)row * EMB + tid * 4;
    bf16 b0,s0,b1,s1,b2,s2,b3,s3;
    split1(out.x,b0,s0); split1(out.y,b1,s1);
    split1(out.z,b2,s2); split1(out.w,b3,s3);
    *(__nv_bfloat162*)(g_hb+o)   = __nv_bfloat162(b0,b1);
    *(__nv_bfloat162*)(g_hb+o+2) = __nv_bfloat162(b2,b3);
    *(__nv_bfloat162*)(g_hs+o)   = __nv_bfloat162(s0,s1);
    *(__nv_bfloat162*)(g_hs+o+2) = __nv_bfloat162(s2,s3);
}

// ---------------- host orchestration ----------------
static void* dsym(const void* s) { void* p; cudaGetSymbolAddress(&p, s); return p; }

extern "C" void kernel_launch(void* const* d_in, const int* in_sizes, int n_in,
                              void* d_out, int out_size)
{
    const void*  x   = d_in[0];
    const float* we  = (const float*)d_in[1];
    const float* pe  = (const float*)d_in[2];
    const float* KQV = (const float*)d_in[3];
    const float* WO  = (const float*)d_in[4];
    const float* Wup = (const float*)d_in[5];
    const float* bup = (const float*)d_in[6];
    const float* Wdn = (const float*)d_in[7];
    const float* bdn = (const float*)d_in[8];
    const float* g1  = (const float*)d_in[9];
    const float* b1  = (const float*)d_in[10];
    const float* g2  = (const float*)d_in[11];
    const float* b2  = (const float*)d_in[12];
    const float* ub  = (const float*)d_in[13];
    float* out = (float*)d_out;

    static bool attr_done = false;
    if (!attr_done) {
        cudaFuncSetAttribute(gemmp<false>, cudaFuncAttributeMaxDynamicSharedMemorySize, 75776);
        cudaFuncSetAttribute(gemmp<true>,  cudaFuncAttributeMaxDynamicSharedMemorySize, 81920);
        attr_done = true;
    }

    float* h    = (float*)dsym(g_h);
    float* qkv  = (float*)dsym(g_qkv);
    float* t    = (float*)dsym(g_t);
    bf16 *hb = (bf16*)dsym(g_hb), *hs = (bf16*)dsym(g_hs);
    bf16 *atb = (bf16*)dsym(g_atb), *ats = (bf16*)dsym(g_ats);
    bf16 *ffb = (bf16*)dsym(g_ffb), *ffs = (bf16*)dsym(g_ffs);
    bf16 *KQVb = (bf16*)dsym(g_KQVb), *KQVs = (bf16*)dsym(g_KQVs);
    bf16 *WOb = (bf16*)dsym(g_WOb), *WOs = (bf16*)dsym(g_WOs);
    bf16 *Wub = (bf16*)dsym(g_Wub), *Wus = (bf16*)dsym(g_Wus);
    bf16 *Wdb = (bf16*)dsym(g_Wdb), *Wds = (bf16*)dsym(g_Wds);
    bf16 *web = (bf16*)dsym(g_web), *wes = (bf16*)dsym(g_wes);

    // one-time-per-launch weight splits (~90us total)
    auto split = [&](const float* s, bf16* db, bf16* ds, size_t n) {
        int grid = (int)min((n / 4 + 255) / 256, (size_t)4096);
        split_kernel<<<grid, 256>>>(s, db, ds, n);
    };
    split(KQV, KQVb, KQVs, (size_t)NLAYER*EMB*3*EMB);
    split(WO,  WOb,  WOs,  (size_t)NLAYER*EMB*EMB);
    split(Wup, Wub,  Wus,  (size_t)NLAYER*EMB*FFD);
    split(Wdn, Wdb,  Wds,  (size_t)NLAYER*FFD*EMB);
    split(we,  web,  wes,  (size_t)VOCAB*EMB);

    probe_kernel<<<1, 32>>>(x);
    embed_kernel<<<MROWS, 256>>>(x, we, pe);

    constexpr size_t SMN = 75776, SMT = 81920;
    for (int l = 0; l < NLAYER; l++) {
        size_t kqvo = (size_t)l * EMB * 3 * EMB;
        size_t woo  = (size_t)l * EMB * EMB;
        size_t wuo  = (size_t)l * EMB * FFD;
        size_t wdo  = (size_t)l * FFD * EMB;
        // qkv = h @ KQV[l]
        gemmp<false><<<dim3(3*EMB/128, MROWS/128), 256, SMN>>>(
            hb, hs, KQVb + kqvo, KQVs + kqvo, nullptr, qkv, nullptr, nullptr,
            MROWS, 3*EMB, EMB, 0);
        // attn
        attn_kernel<<<dim3(SEQ/8, BATCH*NHEAD), 256>>>();
        // t = attn @ WO[l]
        gemmp<false><<<dim3(EMB/128, MROWS/128), 256, SMN>>>(
            atb, ats, WOb + woo, WOs + woo, nullptr, t, nullptr, nullptr,
            MROWS, EMB, EMB, 0);
        ln_res_kernel<<<MROWS, 256>>>(t, g1 + l*EMB, b1 + l*EMB);
        // ff = relu(h @ Wup + bup)  (bf16 pair only)
        gemmp<false><<<dim3(FFD/128, MROWS/128), 256, SMN>>>(
            hb, hs, Wub + wuo, Wus + wuo, bup + (size_t)l*FFD, nullptr, ffb, ffs,
            MROWS, FFD, EMB, 1);
        // t = ff @ Wdn + bdn
        gemmp<false><<<dim3(EMB/128, MROWS/128), 256, SMN>>>(
            ffb, ffs, Wdb + wdo, Wds + wdo, bdn + (size_t)l*EMB, t, nullptr, nullptr,
            MROWS, EMB, FFD, 0);
        ln_res_kernel<<<MROWS, 256>>>(t, g2 + l*EMB, b2 + l*EMB);
    }

    // logits = h @ we^T + ub
    gemmp<true><<<dim3(VOCAB/128, MROWS/128), 256, SMT>>>(
        hb, hs, web, wes, ub, out, nullptr, nullptr,
        MROWS, VOCAB, EMB, 0);
}

// round 14
// speedup vs baseline: 1.8803x; 1.0003x over previous
#include <cuda_runtime.h>
#include <cuda_bf16.h>
#include <cstdint>
#include <cstddef>

// Problem dims (fixed by the dataset)
#define SEQ   2048
#define BATCH 2
#define EMB   1024
#define NHEAD 16
#define HDIM  64
#define FFD   4096
#define NLAYER 4
#define VOCAB 32000
#define MROWS (BATCH*SEQ)   // 4096

typedef __nv_bfloat16 bf16;

// ---------------- scratch (static __device__: allocation-free) ----------------
__device__ float g_h  [(size_t)MROWS * EMB];
__device__ float g_qkv[(size_t)MROWS * 3 * EMB];
__device__ float g_t  [(size_t)MROWS * EMB];
__device__ int   g_is64;

// bf16 big/small pairs: activations
__device__ bf16 g_hb [(size_t)MROWS * EMB],  g_hs [(size_t)MROWS * EMB];
__device__ bf16 g_atb[(size_t)MROWS * EMB],  g_ats[(size_t)MROWS * EMB];
__device__ bf16 g_ffb[(size_t)MROWS * FFD],  g_ffs[(size_t)MROWS * FFD];
// bf16 big/small pairs: weights, TRANSPOSED to [N][K] K-major
__device__ bf16 g_KQVb[(size_t)NLAYER*3*EMB*EMB], g_KQVs[(size_t)NLAYER*3*EMB*EMB];
__device__ bf16 g_WOb [(size_t)NLAYER*EMB*EMB],   g_WOs [(size_t)NLAYER*EMB*EMB];
__device__ bf16 g_Wub [(size_t)NLAYER*FFD*EMB],   g_Wus [(size_t)NLAYER*FFD*EMB];
__device__ bf16 g_Wdb [(size_t)NLAYER*EMB*FFD],   g_Wds [(size_t)NLAYER*EMB*FFD];
__device__ bf16 g_web [(size_t)VOCAB*EMB],        g_wes [(size_t)VOCAB*EMB];

// ---------------- small helpers ----------------
__device__ __forceinline__ void split1(float v, bf16& b, bf16& s) {
    b = __float2bfloat16(v);
    s = __float2bfloat16(v - __bfloat162float(b));
}
__device__ __forceinline__ unsigned smem_u32(const void* p) {
    return (unsigned)__cvta_generic_to_shared(p);
}
__device__ __forceinline__ void cpa16(unsigned d, const void* s) {
    asm volatile("cp.async.cg.shared.global [%0],[%1],16;\n"::"r"(d),"l"(s));
}
__device__ __forceinline__ void cpa_commit() {
    asm volatile("cp.async.commit_group;\n");
}
template<int W> __device__ __forceinline__ void cpa_wait() {
    asm volatile("cp.async.wait_group %0;\n"::"n"(W));
}
__device__ __forceinline__ void ldsm4(unsigned& r0, unsigned& r1,
                                      unsigned& r2, unsigned& r3, unsigned a) {
    asm volatile("ldmatrix.sync.aligned.m8n8.x4.shared.b16 {%0,%1,%2,%3},[%4];"
                 : "=r"(r0), "=r"(r1), "=r"(r2), "=r"(r3) : "r"(a));
}
__device__ __forceinline__ void mma16816(float* c, const unsigned* a,
                                         const unsigned* b) {
    asm volatile(
        "mma.sync.aligned.m16n8k16.row.col.f32.bf16.bf16.f32 "
        "{%0,%1,%2,%3},{%4,%5,%6,%7},{%8,%9},{%0,%1,%2,%3};"
        : "+f"(c[0]), "+f"(c[1]), "+f"(c[2]), "+f"(c[3])
        : "r"(a[0]), "r"(a[1]), "r"(a[2]), "r"(a[3]), "r"(b[0]), "r"(b[1]));
}

// ---------------- token dtype probe ----------------
__global__ void probe_kernel(const void* __restrict__ x) {
    if (threadIdx.x == 0 && blockIdx.x == 0) {
        const unsigned long long* p = (const unsigned long long*)x;
        int ok = 1;
        for (int i = 0; i < 64; i++)
            if (p[i] >= (unsigned long long)VOCAB) { ok = 0; break; }
        g_is64 = ok;
    }
}

// ---------------- split (no transpose): we [V][E] -> pairs ----------------
__global__ __launch_bounds__(256) void split_kernel(
    const float* __restrict__ src, bf16* __restrict__ db,
    bf16* __restrict__ ds, size_t n)
{
    size_t i = ((size_t)blockIdx.x * 256 + threadIdx.x) * 4;
    size_t stride = (size_t)gridDim.x * 1024;
    for (; i < n; i += stride) {
        float4 v = *(const float4*)(src + i);
        bf16 b0,s0,b1,s1,b2,s2,b3,s3;
        split1(v.x,b0,s0); split1(v.y,b1,s1); split1(v.z,b2,s2); split1(v.w,b3,s3);
        *(__nv_bfloat162*)(db+i)   = __nv_bfloat162(b0,b1);
        *(__nv_bfloat162*)(db+i+2) = __nv_bfloat162(b2,b3);
        *(__nv_bfloat162*)(ds+i)   = __nv_bfloat162(s0,s1);
        *(__nv_bfloat162*)(ds+i+2) = __nv_bfloat162(s2,s3);
    }
}

// ---------------- transpose-split: W[l][K][N] fp32 -> Wt[l][N][K] pairs -----
__global__ __launch_bounds__(256) void tsplit_kernel(
    const float* __restrict__ src, bf16* __restrict__ db,
    bf16* __restrict__ ds, int K, int N)
{
    __shared__ float tile[32][33];
    size_t lo = (size_t)blockIdx.z * K * N;
    int n0 = blockIdx.x * 32, k0 = blockIdx.y * 32;
    int tx = threadIdx.x & 31, ty = threadIdx.x >> 5;    // 32 x 8
    #pragma unroll
    for (int r = 0; r < 4; r++)
        tile[ty + 8*r][tx] = src[lo + (size_t)(k0 + ty + 8*r) * N + n0 + tx];
    __syncthreads();
    #pragma unroll
    for (int r = 0; r < 4; r++) {
        float v = tile[tx][ty + 8*r];
        bf16 b, s; split1(v, b, s);
        size_t o = lo + (size_t)(n0 + ty + 8*r) * K + k0 + tx;
        db[o] = b; ds[o] = s;
    }
}

// ---------------- embedding (writes fp32 h + bf16 pair) ----------------
__global__ __launch_bounds__(256) void embed_kernel(
    const void* __restrict__ x, const float* __restrict__ we,
    const float* __restrict__ pe)
{
    int row = blockIdx.x;
    int s = row & (SEQ - 1);
    long long tok = g_is64 ? ((const long long*)x)[row]
                           : (long long)((const int*)x)[row];
    const float4* wr = (const float4*)(we + (size_t)tok * EMB);
    const float4* pr = (const float4*)(pe + (size_t)s * EMB);
    int i = threadIdx.x;
    float4 a = wr[i], b = pr[i];
    float4 v = make_float4(a.x+b.x, a.y+b.y, a.z+b.z, a.w+b.w);
    ((float4*)(g_h + (size_t)row * EMB))[i] = v;
    size_t o = (size_t)row * EMB + i * 4;
    bf16 b0,s0,b1,s1,b2,s2,b3,s3;
    split1(v.x,b0,s0); split1(v.y,b1,s1); split1(v.z,b2,s2); split1(v.w,b3,s3);
    *(__nv_bfloat162*)(g_hb+o)   = __nv_bfloat162(b0,b1);
    *(__nv_bfloat162*)(g_hb+o+2) = __nv_bfloat162(b2,b3);
    *(__nv_bfloat162*)(g_hs+o)   = __nv_bfloat162(s0,s1);
    *(__nv_bfloat162*)(g_hs+o+2) = __nv_bfloat162(s2,s3);
}

// ---------------- HMMA GEMM: C[M,N] = A[M,K] @ B[N,K]^T ---------------------
// Pre-split bf16 pairs, 3 terms (AbBb + AbBs + AsBb), fp32 accum.
// Stage layout (32-K slab): A and B each 128 rows x 128B; a row packs
// [big k0..31 | small k0..31], 16B granules XOR-swizzled: g' = g ^ (row&7).
// 3-stage cp.async ring, 256 threads (2x4 warps, warp tile 64x32), 2 CTA/SM.
// grid.x = M-tile (fast) so same-N CTAs share the B tile in L2.
#define GNS 3
#define GSTG 32768u

__global__ __launch_bounds__(256, 2) void gemm_hs(
    const bf16* __restrict__ Ab, const bf16* __restrict__ As,
    const bf16* __restrict__ Bb, const bf16* __restrict__ Bs,
    const float* __restrict__ bias, float* __restrict__ Cf,
    bf16* __restrict__ Cb, bf16* __restrict__ Cs,
    int M, int N, int K, int relu)
{
    extern __shared__ char dyn[];
    const unsigned s0 = (smem_u32(dyn) + 127u) & ~127u;
    const int tid = threadIdx.x, lane = tid & 31, wid = tid >> 5;
    const int wm = wid >> 2, wn = wid & 3;
    const int mtile = blockIdx.x, ntile = blockIdx.y;

    // per-lane fragment coordinates (non-trans ldsm4 for both A and B)
    const int arow = wm * 64 + (lane & 15);           // + mt*16
    const int ag   = lane >> 4;                       // k-granule select
    const int brow = wn * 32 + (lane & 7) + ((lane >> 4) & 1) * 8; // + n2*16
    const int bg   = (lane >> 3) & 1;
    const int ax7  = arow & 7, bx7 = brow & 7;

    auto load_slab = [&](int slab, int slot) {
        const unsigned base = s0 + slot * GSTG;
        #pragma unroll
        for (int c = 0; c < 8; c++) {
            int ch = tid + c * 256;                   // 0..2047
            bool isA = ch < 1024;
            int r = (ch & 1023) >> 3;
            int g = ch & 7;
            int q = g & 3;                            // 16B chunk within half
            unsigned dst = base + (isA ? 0u : 16384u)
                         + (unsigned)r * 128 + (unsigned)((g ^ (r & 7)) << 4);
            const bf16* src = isA
                ? ((g >> 2) ? As : Ab) + (size_t)(mtile * 128 + r) * K + slab * 32 + q * 8
                : ((g >> 2) ? Bs : Bb) + (size_t)(ntile * 128 + r) * K + slab * 32 + q * 8;
            cpa16(dst, src);
        }
    };

    float acc[4][4][4];
    #pragma unroll
    for (int i = 0; i < 4; i++)
        #pragma unroll
        for (int j = 0; j < 4; j++)
            #pragma unroll
            for (int q = 0; q < 4; q++) acc[i][j][q] = 0.f;

    const int T = K >> 5;
    load_slab(0, 0); cpa_commit();
    load_slab(1, 1); cpa_commit();

    for (int i = 0; i < T; i++) {
        if (i + 2 < T) { load_slab(i + 2, (i + 2) % GNS); cpa_commit(); }
        const int rem = T - 1 - i;
        if (rem >= 2)      cpa_wait<2>();
        else if (rem == 1) cpa_wait<1>();
        else               cpa_wait<0>();
        __syncthreads();

        const unsigned abase = s0 + (i % GNS) * GSTG;
        const unsigned bbase = abase + 16384u;

        #pragma unroll
        for (int ks = 0; ks < 2; ks++) {
            unsigned a[4][4], a2[4][4], bb[4][2], bs[4][2];
            const int gab = ks * 2 + ag;          // A big granule
            const int gas = 4 + ks * 2 + ag;      // A small granule
            const int gbb = ks * 2 + bg;
            const int gbs = 4 + ks * 2 + bg;
            #pragma unroll
            for (int mt = 0; mt < 4; mt++) {
                unsigned ra = abase + (unsigned)(arow + mt * 16) * 128;
                ldsm4(a[mt][0], a[mt][1], a[mt][2], a[mt][3],
                      ra + (unsigned)((gab ^ ax7) << 4));
            }
            #pragma unroll
            for (int n2 = 0; n2 < 2; n2++) {
                unsigned rb = bbase + (unsigned)(brow + n2 * 16) * 128;
                unsigned r0, r1, r2, r3;
                ldsm4(r0, r1, r2, r3, rb + (unsigned)((gbb ^ bx7) << 4));
                bb[2*n2][0] = r0; bb[2*n2][1] = r1;
                bb[2*n2+1][0] = r2; bb[2*n2+1][1] = r3;
            }
            #pragma unroll
            for (int mt = 0; mt < 4; mt++)
                #pragma unroll
                for (int nt = 0; nt < 4; nt++)
                    mma16816(acc[mt][nt], a[mt], bb[nt]);       // Ab*Bb
            #pragma unroll
            for (int n2 = 0; n2 < 2; n2++) {
                unsigned rb = bbase + (unsigned)(brow + n2 * 16) * 128;
                unsigned r0, r1, r2, r3;
                ldsm4(r0, r1, r2, r3, rb + (unsigned)((gbs ^ bx7) << 4));
                bs[2*n2][0] = r0; bs[2*n2][1] = r1;
                bs[2*n2+1][0] = r2; bs[2*n2+1][1] = r3;
            }
            #pragma unroll
            for (int mt = 0; mt < 4; mt++)
                #pragma unroll
                for (int nt = 0; nt < 4; nt++)
                    mma16816(acc[mt][nt], a[mt], bs[nt]);       // Ab*Bs
            #pragma unroll
            for (int mt = 0; mt < 4; mt++) {
                unsigned ra = abase + (unsigned)(arow + mt * 16) * 128;
                ldsm4(a2[mt][0], a2[mt][1], a2[mt][2], a2[mt][3],
                      ra + (unsigned)((gas ^ ax7) << 4));
            }
            #pragma unroll
            for (int mt = 0; mt < 4; mt++)
                #pragma unroll
                for (int nt = 0; nt < 4; nt++)
                    mma16816(acc[mt][nt], a2[mt], bb[nt]);      // As*Bb
        }
        __syncthreads();
    }

    // ---- epilogue ----
    const int g = lane >> 2, t2 = (lane & 3) * 2;
    #pragma unroll
    for (int mt = 0; mt < 4; mt++) {
        int row = mtile * 128 + wm * 64 + mt * 16 + g;
        #pragma unroll
        for (int nt = 0; nt < 4; nt++) {
            int col = ntile * 128 + wn * 32 + nt * 8 + t2;
            float bb0 = 0.f, bb1 = 0.f;
            if (bias) { bb0 = bias[col]; bb1 = bias[col + 1]; }
            float v0 = acc[mt][nt][0] + bb0, v1 = acc[mt][nt][1] + bb1;
            float v2 = acc[mt][nt][2] + bb0, v3 = acc[mt][nt][3] + bb1;
            if (relu) {
                v0 = fmaxf(v0, 0.f); v1 = fmaxf(v1, 0.f);
                v2 = fmaxf(v2, 0.f); v3 = fmaxf(v3, 0.f);
            }
            if (Cf) {
                *(float2*)(Cf + (size_t)row * N + col) = make_float2(v0, v1);
                *(float2*)(Cf + (size_t)(row + 8) * N + col) = make_float2(v2, v3);
            }
            if (Cb) {
                bf16 hb0,hs0,hb1,hs1,hb2,hs2,hb3,hs3;
                split1(v0,hb0,hs0); split1(v1,hb1,hs1);
                split1(v2,hb2,hs2); split1(v3,hb3,hs3);
                size_t o = (size_t)row * N + col;
                size_t o8 = (size_t)(row + 8) * N + col;
                *(__nv_bfloat162*)(Cb+o)  = __nv_bfloat162(hb0,hb1);
                *(__nv_bfloat162*)(Cb+o8) = __nv_bfloat162(hb2,hb3);
                *(__nv_bfloat162*)(Cs+o)  = __nv_bfloat162(hs0,hs1);
                *(__nv_bfloat162*)(Cs+o8) = __nv_bfloat162(hs2,hs3);
            }
        }
    }
}

// ---------------- fused causal flash-attention (fp32, pair output) ----------
__global__ __launch_bounds__(256) void attn_kernel()
{
    int bh = blockIdx.y;
    int b = bh >> 4, hh = bh & 15;
    int qbase = blockIdx.x * 8;
    int w = threadIdx.x >> 5, lane = threadIdx.x & 31;
    int qrow = qbase + w;

    __shared__ float Qs[8][64];
    __shared__ float Kst[64][33];
    __shared__ float Vs[32][64];

    const float* qkv = g_qkv;
    for (int i = threadIdx.x; i < 8 * 64; i += 256) {
        int r = i >> 6, d = i & 63;
        Qs[r][d] = qkv[((size_t)b * SEQ + qbase + r) * 3072 + hh * 192 + 64 + d];
    }

    float m = -1e30f, lsum = 0.f, acc0 = 0.f, acc1 = 0.f;
    for (int kt = 0; kt < qbase + 8; kt += 32) {
        __syncthreads();
        for (int i = threadIdx.x; i < 32 * 64; i += 256) {
            int kk = i >> 6, d = i & 63;
            size_t off = ((size_t)b * SEQ + kt + kk) * 3072 + hh * 192;
            Kst[d][kk] = qkv[off + d];
            Vs[kk][d]  = qkv[off + 128 + d];
        }
        __syncthreads();

        float s = 0.f;
        #pragma unroll
        for (int d = 0; d < 64; d++) s += Qs[w][d] * Kst[d][lane];
        s *= 0.125f;
        if (kt + lane > qrow) s = -1e30f;

        float tmax = s;
        for (int o = 16; o; o >>= 1) tmax = fmaxf(tmax, __shfl_xor_sync(~0u, tmax, o));
        float mnew = fmaxf(m, tmax);
        float corr = __expf(m - mnew);
        float p = __expf(s - mnew);
        float ps = p;
        for (int o = 16; o; o >>= 1) ps += __shfl_xor_sync(~0u, ps, o);
        lsum = lsum * corr + ps;
        acc0 *= corr; acc1 *= corr;
        #pragma unroll
        for (int j = 0; j < 32; j++) {
            float pj = __shfl_sync(~0u, p, j);
            acc0 += pj * Vs[j][lane];
            acc1 += pj * Vs[j][lane + 32];
        }
        m = mnew;
    }
    float inv = 1.f / lsum;
    size_t o = ((size_t)b * SEQ + qrow) * EMB + hh * 64;
    bf16 b0,s0,b1,s1;
    split1(acc0 * inv, b0, s0);
    split1(acc1 * inv, b1, s1);
    g_atb[o + lane] = b0;       g_ats[o + lane] = s0;
    g_atb[o + 32 + lane] = b1;  g_ats[o + 32 + lane] = s1;
}

// ---------------- fused LayerNorm + residual (fp32 h + pair) ----------------
__global__ __launch_bounds__(256) void ln_res_kernel(
    const float* __restrict__ y, const float* __restrict__ g,
    const float* __restrict__ b)
{
    int row = blockIdx.x;
    int tid = threadIdx.x;
    const float4* yr = (const float4*)(y + (size_t)row * EMB);
    float4* hr = (float4*)(g_h + (size_t)row * EMB);

    float4 v = yr[tid];
    float s  = v.x + v.y + v.z + v.w;
    float sq = v.x*v.x + v.y*v.y + v.z*v.z + v.w*v.w;
    int lane = tid & 31, wid = tid >> 5;
    for (int o = 16; o; o >>= 1) {
        s  += __shfl_xor_sync(~0u, s,  o);
        sq += __shfl_xor_sync(~0u, sq, o);
    }
    __shared__ float sh[16];
    __shared__ float mu_s, rs_s;
    if (lane == 0) { sh[wid] = s; sh[8 + wid] = sq; }
    __syncthreads();
    if (tid == 0) {
        float ts = 0.f, tq = 0.f;
        for (int i = 0; i < 8; i++) { ts += sh[i]; tq += sh[8 + i]; }
        float mu = ts * (1.f / EMB);
        float var = tq * (1.f / EMB) - mu * mu;
        mu_s = mu;
        rs_s = rsqrtf(var + 1e-6f);
    }
    __syncthreads();
    float mu = mu_s, rs = rs_s;
    const float4 gg = ((const float4*)g)[tid];
    const float4 bb = ((const float4*)b)[tid];
    float4 res = hr[tid];
    float4 out;
    out.x = (v.x - mu) * rs * gg.x + bb.x + res.x;
    out.y = (v.y - mu) * rs * gg.y + bb.y + res.y;
    out.z = (v.z - mu) * rs * gg.z + bb.z + res.z;
    out.w = (v.w - mu) * rs * gg.w + bb.w + res.w;
    hr[tid] = out;
    size_t o = (size_t)row * EMB + tid * 4;
    bf16 b0,s0,b1,s1,b2,s2,b3,s3;
    split1(out.x,b0,s0); split1(out.y,b1,s1);
    split1(out.z,b2,s2); split1(out.w,b3,s3);
    *(__nv_bfloat162*)(g_hb+o)   = __nv_bfloat162(b0,b1);
    *(__nv_bfloat162*)(g_hb+o+2) = __nv_bfloat162(b2,b3);
    *(__nv_bfloat162*)(g_hs+o)   = __nv_bfloat162(s0,s1);
    *(__nv_bfloat162*)(g_hs+o+2) = __nv_bfloat162(s2,s3);
}

// ---------------- host orchestration ----------------
static void* dsym(const void* s) { void* p; cudaGetSymbolAddress(&p, s); return p; }

extern "C" void kernel_launch(void* const* d_in, const int* in_sizes, int n_in,
                              void* d_out, int out_size)
{
    const void*  x   = d_in[0];
    const float* we  = (const float*)d_in[1];
    const float* pe  = (const float*)d_in[2];
    const float* KQV = (const float*)d_in[3];
    const float* WO  = (const float*)d_in[4];
    const float* Wup = (const float*)d_in[5];
    const float* bup = (const float*)d_in[6];
    const float* Wdn = (const float*)d_in[7];
    const float* bdn = (const float*)d_in[8];
    const float* g1  = (const float*)d_in[9];
    const float* b1  = (const float*)d_in[10];
    const float* g2  = (const float*)d_in[11];
    const float* b2  = (const float*)d_in[12];
    const float* ub  = (const float*)d_in[13];
    float* out = (float*)d_out;

    constexpr size_t GSMEM = (size_t)GNS * GSTG + 128;     // ~96.1 KB
    static bool attr_done = false;
    if (!attr_done) {
        cudaFuncSetAttribute(gemm_hs, cudaFuncAttributeMaxDynamicSharedMemorySize,
                             (int)GSMEM);
        attr_done = true;
    }

    float* qkv  = (float*)dsym(g_qkv);
    float* t    = (float*)dsym(g_t);
    bf16 *hb = (bf16*)dsym(g_hb), *hs = (bf16*)dsym(g_hs);
    bf16 *atb = (bf16*)dsym(g_atb), *ats = (bf16*)dsym(g_ats);
    bf16 *ffb = (bf16*)dsym(g_ffb), *ffs = (bf16*)dsym(g_ffs);
    bf16 *KQVb = (bf16*)dsym(g_KQVb), *KQVs = (bf16*)dsym(g_KQVs);
    bf16 *WOb = (bf16*)dsym(g_WOb), *WOs = (bf16*)dsym(g_WOs);
    bf16 *Wub = (bf16*)dsym(g_Wub), *Wus = (bf16*)dsym(g_Wus);
    bf16 *Wdb = (bf16*)dsym(g_Wdb), *Wds = (bf16*)dsym(g_Wds);
    bf16 *web = (bf16*)dsym(g_web), *wes = (bf16*)dsym(g_wes);

    // Launch order puts the first gemm_hs at profile slot 5 (-s 5 -c 1).
    probe_kernel<<<1, 32>>>(x);                                            // 0
    embed_kernel<<<MROWS, 256>>>(x, we, pe);                               // 1
    tsplit_kernel<<<dim3(3*EMB/32, EMB/32, NLAYER), 256>>>(KQV, KQVb, KQVs, EMB, 3*EMB); // 2
    tsplit_kernel<<<dim3(EMB/32,  EMB/32, NLAYER), 256>>>(WO,  WOb,  WOs,  EMB, EMB);    // 3
    tsplit_kernel<<<dim3(FFD/32,  EMB/32, NLAYER), 256>>>(Wup, Wub,  Wus,  EMB, FFD);    // 4

    bool first = true;
    for (int l = 0; l < NLAYER; l++) {
        size_t kqvo = (size_t)l * EMB * 3 * EMB;
        size_t woo  = (size_t)l * EMB * EMB;
        size_t wuo  = (size_t)l * EMB * FFD;
        size_t wdo  = (size_t)l * FFD * EMB;
        // qkv = h @ KQV[l]^T-layout      M=4096 N=3072 K=1024   (slot 5 on l=0)
        gemm_hs<<<dim3(MROWS/128, 3*EMB/128), 256, GSMEM>>>(
            hb, hs, KQVb + kqvo, KQVs + kqvo, nullptr, qkv, nullptr, nullptr,
            MROWS, 3*EMB, EMB, 0);
        if (first) {
            // remaining one-time splits, overlapped after the first gemm
            tsplit_kernel<<<dim3(EMB/32, FFD/32, NLAYER), 256>>>(Wdn, Wdb, Wds, FFD, EMB);
            split_kernel<<<4096, 256>>>(we, web, wes, (size_t)VOCAB*EMB);
            first = false;
        }
        attn_kernel<<<dim3(SEQ/8, BATCH*NHEAD), 256>>>();
        // t = attn @ WO[l]               M=4096 N=1024 K=1024
        gemm_hs<<<dim3(MROWS/128, EMB/128), 256, GSMEM>>>(
            atb, ats, WOb + woo, WOs + woo, nullptr, t, nullptr, nullptr,
            MROWS, EMB, EMB, 0);
        ln_res_kernel<<<MROWS, 256>>>(t, g1 + l*EMB, b1 + l*EMB);
        // ff = relu(h @ Wup + bup)       M=4096 N=4096 K=1024 (pair out)
        gemm_hs<<<dim3(MROWS/128, FFD/128), 256, GSMEM>>>(
            hb, hs, Wub + wuo, Wus + wuo, bup + (size_t)l*FFD, nullptr, ffb, ffs,
            MROWS, FFD, EMB, 1);
        // t = ff @ Wdn + bdn             M=4096 N=1024 K=4096
        gemm_hs<<<dim3(MROWS/128, EMB/128), 256, GSMEM>>>(
            ffb, ffs, Wdb + wdo, Wds + wdo, bdn + (size_t)l*EMB, t, nullptr, nullptr,
            MROWS, EMB, FFD, 0);
        ln_res_kernel<<<MROWS, 256>>>(t, g2 + l*EMB, b2 + l*EMB);
    }

    // logits = h @ we^T + ub             M=4096 N=32000 K=1024
    gemm_hs<<<dim3(MROWS/128, VOCAB/128), 256, GSMEM>>>(
        hb, hs, web, wes, ub, out, nullptr, nullptr,
        MROWS, VOCAB, EMB, 0);
}